// round 13
// baseline (speedup 1.0000x reference)
#include <cuda_runtime.h>
#include <math.h>

#define NB 15
#define NC 4096
#define BATCH 512
#define CCH 64                  // c-chunks of 64 floats; grid = (64, 15) = 960 blocks
#define NGROUP (NB * CCH)       // 960

// Scratch (allocation-free): 7.5 KB of per-block results
__device__ float2       g_bpart[NGROUP];   // [b][cc] -> {sum m, sum m^2} over 64 channels
__device__ unsigned int g_ctr;             // zero-init; reset by last block

// ---------------------------------------------------------------------------
// Single kernel. Each block fully reduces 512 batch rows x 64 channels of one
// base (128 KB, coalesced: warp = 2 rows x 256 B). Threads = 16 float4-lanes
// x 16 z-slices of 32 rows -> 32 loads/thread in batches of 8. ONE barrier,
// then warp 0: 16 lanes gather their 16 slice-partials from smem, form
// (sum m, sum m^2), width-16 shuffle, 8-byte store + arrive. The LAST arriver
// reduces the 960 L2-hot float2s and computes the loss.
// grid = (CCH, NB), block = 256
// ---------------------------------------------------------------------------
__global__ void __launch_bounds__(256) k_loss(const float* __restrict__ in,
                                              float* __restrict__ out)
{
    const int cc    = blockIdx.x;
    const int b     = blockIdx.y;
    const int tid   = threadIdx.x;
    const int lane4 = tid & 15;        // 16 float4 lanes = 64 channels
    const int zsl   = tid >> 4;        // 16 z-slices of 32 rows
    const int g     = b * CCH + cc;

    // ---- phase A: reduce 32 rows for this (lane4, zsl) ----
    const size_t rs4 = (size_t)NB * NC / 4;   // float4 stride between batch rows
    const float4* p = (const float4*)(in + ((size_t)(zsl * 32) * NB + b) * NC
                                         + cc * 64 + lane4 * 4);

    float4 a0 = make_float4(0.f, 0.f, 0.f, 0.f);
    float4 a1 = a0, a2 = a0, a3 = a0;

    #pragma unroll
    for (int i = 0; i < 32; i += 8) {
        float4 v0 = __ldcs(p + (size_t)(i + 0) * rs4);
        float4 v1 = __ldcs(p + (size_t)(i + 1) * rs4);
        float4 v2 = __ldcs(p + (size_t)(i + 2) * rs4);
        float4 v3 = __ldcs(p + (size_t)(i + 3) * rs4);
        float4 v4 = __ldcs(p + (size_t)(i + 4) * rs4);
        float4 v5 = __ldcs(p + (size_t)(i + 5) * rs4);
        float4 v6 = __ldcs(p + (size_t)(i + 6) * rs4);
        float4 v7 = __ldcs(p + (size_t)(i + 7) * rs4);
        a0.x += v0.x; a0.y += v0.y; a0.z += v0.z; a0.w += v0.w;
        a1.x += v1.x; a1.y += v1.y; a1.z += v1.z; a1.w += v1.w;
        a2.x += v2.x; a2.y += v2.y; a2.z += v2.z; a2.w += v2.w;
        a3.x += v3.x; a3.y += v3.y; a3.z += v3.z; a3.w += v3.w;
        a0.x += v4.x; a0.y += v4.y; a0.z += v4.z; a0.w += v4.w;
        a1.x += v5.x; a1.y += v5.y; a1.z += v5.z; a1.w += v5.w;
        a2.x += v6.x; a2.y += v6.y; a2.z += v6.z; a2.w += v6.w;
        a3.x += v7.x; a3.y += v7.y; a3.z += v7.z; a3.w += v7.w;
    }

    float4 acc;
    acc.x = (a0.x + a1.x) + (a2.x + a3.x);
    acc.y = (a0.y + a1.y) + (a2.y + a3.y);
    acc.z = (a0.z + a1.z) + (a2.z + a3.z);
    acc.w = (a0.w + a1.w) + (a2.w + a3.w);

    // ---- ONE barrier; warp 0 gathers the 16 slice-partials per lane ----
    __shared__ float4 sh[256];        // [slice][lane]
    sh[tid] = acc;
    __syncthreads();

    float s = 0.f, s2 = 0.f;
    if (tid < 32) {
        if (tid < 16) {
            // sum slices 0..15 for this lane, fixed order; conflict-free LDS
            float4 t = sh[tid];
            #pragma unroll
            for (int k = 1; k < 16; k++) {
                float4 u = sh[k * 16 + tid];
                t.x += u.x; t.y += u.y; t.z += u.z; t.w += u.w;
            }
            const float inv_batch = 1.0f / (float)BATCH;   // exact
            float m0 = t.x * inv_batch;
            float m1 = t.y * inv_batch;
            float m2 = t.z * inv_batch;
            float m3 = t.w * inv_batch;
            s  = (m0 + m1) + (m2 + m3);
            s2 = fmaf(m0, m0, m1 * m1) + fmaf(m2, m2, m3 * m3);
        }
        // width-16 segmented shuffles executed by the FULL warp (no divergence)
        #pragma unroll
        for (int off = 8; off > 0; off >>= 1) {
            s  += __shfl_down_sync(0xffffffffu, s,  off, 16);
            s2 += __shfl_down_sync(0xffffffffu, s2, off, 16);
        }
    }

    __shared__ int sh_last;
    if (tid == 0) {
        g_bpart[g] = make_float2(s, s2);   // 8-byte store
        __threadfence();                   // cheap: only 8 B to drain
        unsigned int old = atomicAdd(&g_ctr, 1u);
        sh_last = (old == NGROUP - 1) ? 1 : 0;
    }
    __syncthreads();
    if (!sh_last) return;

    // =========== last arriver: reduce 960 float2s + final loss ===========
    __threadfence();   // acquire all blocks' g_bpart

    __shared__ float sh_mean[NB], sh_std[NB];

    // base = tid>>4 (0..15), part = tid&15; 4 sequential float2 loads each.
    // ALL 256 threads execute the shuffles (width-16 segments, no divergence).
    {
        const int base = tid >> 4;
        const int part = tid & 15;
        float s = 0.f, s2 = 0.f;
        if (base < NB) {
            const float2* q = &g_bpart[base * CCH + part * 4];
            #pragma unroll
            for (int k = 0; k < 4; k++) { float2 v = q[k]; s += v.x; s2 += v.y; }
        }
        #pragma unroll
        for (int off = 8; off > 0; off >>= 1) {
            s  += __shfl_down_sync(0xffffffffu, s,  off, 16);
            s2 += __shfl_down_sync(0xffffffffu, s2, off, 16);
        }
        if (base < NB && part == 0) {
            float mean = s * (1.0f / (float)NC);           // exact scale
            float var  = (s2 - s * s * (1.0f / (float)NC)) * (1.0f / (float)(NC - 1));
            if (var < 0.f) var = 0.f;
            sh_mean[base] = mean;
            sh_std[base]  = sqrtf(var);
        }
    }
    __syncthreads();
    if (tid >= 32) return;

    // ---- warp 0: group stats + pairwise-exp loss (fp32) ----
    const int l = tid;
    // groups: [0,3) [3,5) [5,6) [6,10) [10,12) [12,15)
    const int starts[7] = {0, 3, 5, 6, 10, 12, 15};
    const int G = 6;
    const int pi[15] = {0,0,0,0,0, 1,1,1,1, 2,2,2, 3,3, 4};
    const int pj[15] = {1,2,3,4,5, 2,3,4,5, 3,4,5, 4,5, 5};

    __shared__ float sh_ss[6], sh_mn[6], sh_msum[6], sh_pair[15], sh_lt[6];

    if (l < G) {
        const int s0 = starts[l], s1 = starts[l + 1];
        const int ng = s1 - s0;
        if (ng == 1) {
            sh_ss[l]   = sh_std[s0];
            sh_msum[l] = sh_mean[s0];
            sh_mn[l]   = sh_mean[s0];
        } else {
            float ms = 0.f, mm = 0.f;
            for (int k = s0; k < s1; k++) { ms += sh_std[k]; mm += sh_mean[k]; }
            ms /= (float)ng; mm /= (float)ng;
            float vs = 0.f, vm = 0.f;
            for (int k = s0; k < s1; k++) {
                float d = sh_std[k]  - ms; vs = fmaf(d, d, vs);
                float e = sh_mean[k] - mm; vm = fmaf(e, e, vm);
            }
            sh_ss[l]   = sqrtf(vs / (float)(ng - 1));
            sh_msum[l] = sqrtf(vm / (float)(ng - 1));
            sh_mn[l]   = mm;
        }
    }
    __syncwarp();

    if (l < 15) {
        float d1 = sh_ss[pi[l]] - sh_ss[pj[l]];
        float d2 = sh_mn[pi[l]] - sh_mn[pj[l]];
        sh_pair[l] = expf(d1 * d1) + expf(d2 * d2);   // MEAN_STD = 1.0
    }
    __syncwarp();

    if (l < G) {
        float subloss = 5e-5f;
        #pragma unroll
        for (int p = 0; p < 15; p++)
            if (pi[p] == l) subloss += sh_pair[p];
        sh_lt[l] = logf(1.0f + sh_msum[l] / (subloss + sh_msum[l]));
    }
    __syncwarp();

    if (l == 0) {
        float loss = 0.f;
        #pragma unroll
        for (int g2 = 0; g2 < G; g2++) loss += sh_lt[g2];
        out[0] = loss;
        g_ctr = 0;   // reset for next graph replay
    }
}

// ---------------------------------------------------------------------------
extern "C" void kernel_launch(void* const* d_in, const int* in_sizes, int n_in,
                              void* d_out, int out_size)
{
    const float* meta1 = (const float*)d_in[0];

    dim3 g(CCH, NB);   // (64, 15) = 960 blocks, 256 threads each
    k_loss<<<g, 256>>>(meta1, (float*)d_out);
}

// round 14
// speedup vs baseline: 1.1509x; 1.1509x over previous
#include <cuda_runtime.h>
#include <math.h>

#define NB 15
#define NC 4096
#define BATCH 512
#define CCH 32                  // c-chunks of 128 floats; grid = (32, 15) = 480 blocks
#define NGROUP (NB * CCH)       // 480 -> single resident wave (3.24 blocks/SM)

// Scratch (allocation-free): 3.75 KB of per-block results
__device__ float2       g_bpart[NGROUP];   // [b][cc] -> {sum m, sum m^2} over 128 channels
__device__ unsigned int g_ctr;             // zero-init; reset by last block

// ---------------------------------------------------------------------------
// Single kernel, single wave. Each block fully reduces 512 rows x 128 channels
// of one base (256 KB; warp = one coalesced 512 B row). Threads = 32 float4-
// lanes x 8 z-slices of 64 rows -> 64 loads/thread in 8-deep batches (long
// uninterrupted streaming, zero block-round transitions). ONE barrier, then
// warp 0 folds the 8 slice-partials, forms (sum m, sum m^2), stores 8 bytes,
// arrives. The LAST arriver reduces 480 L2-hot float2s + computes the loss.
// grid = (CCH, NB), block = 256
// ---------------------------------------------------------------------------
__global__ void __launch_bounds__(256) k_loss(const float* __restrict__ in,
                                              float* __restrict__ out)
{
    const int cc   = blockIdx.x;
    const int b    = blockIdx.y;
    const int tid  = threadIdx.x;
    const int lane = tid & 31;         // 32 float4 lanes = 128 channels
    const int zsl  = tid >> 5;         // 8 z-slices of 64 rows
    const int g    = b * CCH + cc;

    // ---- phase A: reduce 64 rows for this (lane, zsl) ----
    const size_t rs4 = (size_t)NB * NC / 4;   // float4 stride between batch rows
    const float4* p = (const float4*)(in + ((size_t)(zsl * 64) * NB + b) * NC
                                         + cc * 128 + lane * 4);

    float4 a0 = make_float4(0.f, 0.f, 0.f, 0.f);
    float4 a1 = a0, a2 = a0, a3 = a0;

    #pragma unroll 2
    for (int i = 0; i < 64; i += 8) {
        float4 v0 = __ldcs(p + (size_t)(i + 0) * rs4);
        float4 v1 = __ldcs(p + (size_t)(i + 1) * rs4);
        float4 v2 = __ldcs(p + (size_t)(i + 2) * rs4);
        float4 v3 = __ldcs(p + (size_t)(i + 3) * rs4);
        float4 v4 = __ldcs(p + (size_t)(i + 4) * rs4);
        float4 v5 = __ldcs(p + (size_t)(i + 5) * rs4);
        float4 v6 = __ldcs(p + (size_t)(i + 6) * rs4);
        float4 v7 = __ldcs(p + (size_t)(i + 7) * rs4);
        a0.x += v0.x; a0.y += v0.y; a0.z += v0.z; a0.w += v0.w;
        a1.x += v1.x; a1.y += v1.y; a1.z += v1.z; a1.w += v1.w;
        a2.x += v2.x; a2.y += v2.y; a2.z += v2.z; a2.w += v2.w;
        a3.x += v3.x; a3.y += v3.y; a3.z += v3.z; a3.w += v3.w;
        a0.x += v4.x; a0.y += v4.y; a0.z += v4.z; a0.w += v4.w;
        a1.x += v5.x; a1.y += v5.y; a1.z += v5.z; a1.w += v5.w;
        a2.x += v6.x; a2.y += v6.y; a2.z += v6.z; a2.w += v6.w;
        a3.x += v7.x; a3.y += v7.y; a3.z += v7.z; a3.w += v7.w;
    }

    float4 acc;
    acc.x = (a0.x + a1.x) + (a2.x + a3.x);
    acc.y = (a0.y + a1.y) + (a2.y + a3.y);
    acc.z = (a0.z + a1.z) + (a2.z + a3.z);
    acc.w = (a0.w + a1.w) + (a2.w + a3.w);

    // ---- ONE barrier; warp 0 folds the 8 slice-partials per lane ----
    __shared__ float4 sh[256];        // [slice][lane]
    sh[tid] = acc;
    __syncthreads();

    float s = 0.f, s2 = 0.f;
    if (tid < 32) {
        // sum slices 0..7 for this lane, fixed order; conflict-free LDS
        float4 t = sh[lane];
        #pragma unroll
        for (int k = 1; k < 8; k++) {
            float4 u = sh[k * 32 + lane];
            t.x += u.x; t.y += u.y; t.z += u.z; t.w += u.w;
        }
        const float inv_batch = 1.0f / (float)BATCH;   // exact
        float m0 = t.x * inv_batch;
        float m1 = t.y * inv_batch;
        float m2 = t.z * inv_batch;
        float m3 = t.w * inv_batch;
        s  = (m0 + m1) + (m2 + m3);
        s2 = fmaf(m0, m0, m1 * m1) + fmaf(m2, m2, m3 * m3);
        // full-warp width-32 reduction (fixed order)
        #pragma unroll
        for (int off = 16; off > 0; off >>= 1) {
            s  += __shfl_down_sync(0xffffffffu, s,  off);
            s2 += __shfl_down_sync(0xffffffffu, s2, off);
        }
    }

    __shared__ int sh_last;
    if (tid == 0) {
        g_bpart[g] = make_float2(s, s2);   // 8-byte store
        __threadfence();
        unsigned int old = atomicAdd(&g_ctr, 1u);
        sh_last = (old == NGROUP - 1) ? 1 : 0;
    }
    __syncthreads();
    if (!sh_last) return;

    // =========== last arriver: reduce 480 float2s + final loss ===========
    __threadfence();   // acquire all blocks' g_bpart

    __shared__ float sh_mean[NB], sh_std[NB];

    // base = tid>>4 (0..15), part = tid&15; 2 sequential float2 loads each.
    // ALL 256 threads execute the shuffles (width-16 segments, no divergence).
    {
        const int base = tid >> 4;
        const int part = tid & 15;
        float s = 0.f, s2 = 0.f;
        if (base < NB) {
            float2 v0 = g_bpart[base * CCH + part * 2 + 0];
            float2 v1 = g_bpart[base * CCH + part * 2 + 1];
            s  = v0.x + v1.x;
            s2 = v0.y + v1.y;
        }
        #pragma unroll
        for (int off = 8; off > 0; off >>= 1) {
            s  += __shfl_down_sync(0xffffffffu, s,  off, 16);
            s2 += __shfl_down_sync(0xffffffffu, s2, off, 16);
        }
        if (base < NB && part == 0) {
            float mean = s * (1.0f / (float)NC);           // exact scale
            float var  = (s2 - s * s * (1.0f / (float)NC)) * (1.0f / (float)(NC - 1));
            if (var < 0.f) var = 0.f;
            sh_mean[base] = mean;
            sh_std[base]  = sqrtf(var);
        }
    }
    __syncthreads();
    if (tid >= 32) return;

    // ---- warp 0: group stats + pairwise-exp loss (fp32) ----
    const int l = tid;
    // groups: [0,3) [3,5) [5,6) [6,10) [10,12) [12,15)
    const int starts[7] = {0, 3, 5, 6, 10, 12, 15};
    const int G = 6;
    const int pi[15] = {0,0,0,0,0, 1,1,1,1, 2,2,2, 3,3, 4};
    const int pj[15] = {1,2,3,4,5, 2,3,4,5, 3,4,5, 4,5, 5};

    __shared__ float sh_ss[6], sh_mn[6], sh_msum[6], sh_pair[15], sh_lt[6];

    if (l < G) {
        const int s0 = starts[l], s1 = starts[l + 1];
        const int ng = s1 - s0;
        if (ng == 1) {
            sh_ss[l]   = sh_std[s0];
            sh_msum[l] = sh_mean[s0];
            sh_mn[l]   = sh_mean[s0];
        } else {
            float ms = 0.f, mm = 0.f;
            for (int k = s0; k < s1; k++) { ms += sh_std[k]; mm += sh_mean[k]; }
            ms /= (float)ng; mm /= (float)ng;
            float vs = 0.f, vm = 0.f;
            for (int k = s0; k < s1; k++) {
                float d = sh_std[k]  - ms; vs = fmaf(d, d, vs);
                float e = sh_mean[k] - mm; vm = fmaf(e, e, vm);
            }
            sh_ss[l]   = sqrtf(vs / (float)(ng - 1));
            sh_msum[l] = sqrtf(vm / (float)(ng - 1));
            sh_mn[l]   = mm;
        }
    }
    __syncwarp();

    if (l < 15) {
        float d1 = sh_ss[pi[l]] - sh_ss[pj[l]];
        float d2 = sh_mn[pi[l]] - sh_mn[pj[l]];
        sh_pair[l] = expf(d1 * d1) + expf(d2 * d2);   // MEAN_STD = 1.0
    }
    __syncwarp();

    if (l < G) {
        float subloss = 5e-5f;
        #pragma unroll
        for (int p = 0; p < 15; p++)
            if (pi[p] == l) subloss += sh_pair[p];
        sh_lt[l] = logf(1.0f + sh_msum[l] / (subloss + sh_msum[l]));
    }
    __syncwarp();

    if (l == 0) {
        float loss = 0.f;
        #pragma unroll
        for (int g2 = 0; g2 < G; g2++) loss += sh_lt[g2];
        out[0] = loss;
        g_ctr = 0;   // reset for next graph replay
    }
}

// ---------------------------------------------------------------------------
extern "C" void kernel_launch(void* const* d_in, const int* in_sizes, int n_in,
                              void* d_out, int out_size)
{
    const float* meta1 = (const float*)d_in[0];

    dim3 g(CCH, NB);   // (32, 15) = 480 blocks, 256 threads each = single wave
    k_loss<<<g, 256>>>(meta1, (float*)d_out);
}